// round 10
// baseline (speedup 1.0000x reference)
#include <cuda_runtime.h>
#include <math.h>

typedef unsigned long long ull;

// Problem constants (fixed shapes)
#define B_    8
#define T_    1000
#define IN_   80
#define CONV_ 256
#define CCEP_ 222
#define HOP_  256
#define WIN_  512
#define NF_   1024
#define PAD_  401
#define ZLEN_ 256000

#define N1_ (80  * 3 * 256)
#define N2_ (32  * 3 * 256)
#define N3_ (32  * 3 * 256)
#define N4_ (256 * 3 * 222)

// ---------------- static device scratch ----------------
__device__ float  g_bufA[B_ * T_ * CONV_];
__device__ float  g_bufB[B_ * T_ * CONV_];
__device__ float  g_cq  [B_ * T_ * CCEP_];
__device__ float  g_imp [B_ * T_ * NF_];
__device__ float  g_zw  [B_ * T_ * WIN_];
__device__ float2 g_tw  [512];
// transposed + duplicated weights: WT2[(i*3+k)*COUT + o] = (w, w)
__device__ __align__(16) float2 g_wT1[N1_];
__device__ __align__(16) float2 g_wT2[N2_];
__device__ __align__(16) float2 g_wT3[N3_];
__device__ __align__(16) float2 g_wT4[N4_];

// ---------------- packed f32x2 helpers ----------------
__device__ __forceinline__ ull pack2(float lo, float hi) {
    ull r; asm("mov.b64 %0, {%1,%2};" : "=l"(r) : "f"(lo), "f"(hi)); return r;
}
__device__ __forceinline__ void unpack2(ull v, float& lo, float& hi) {
    asm("mov.b64 {%0,%1}, %2;" : "=f"(lo), "=f"(hi) : "l"(v));
}
__device__ __forceinline__ ull fma2(ull a, ull b, ull c) {
    ull d; asm("fma.rn.f32x2 %0, %1, %2, %3;" : "=l"(d) : "l"(a), "l"(b), "l"(c)); return d;
}
// (a.hi, b.lo)
__device__ __forceinline__ ull hilo(ull a, ull b) {
    float al, ah, bl, bh;
    unpack2(a, al, ah); unpack2(b, bl, bh);
    return pack2(ah, bl);
}

// ---------------- fused prep: twiddles + 4 weight transposes ----------------
__global__ void prep_kernel(const float* __restrict__ W1, const float* __restrict__ W2,
                            const float* __restrict__ W3, const float* __restrict__ W4) {
    int gid = blockIdx.x * 256 + threadIdx.x;
    if (gid < 512) {
        float s, c;
        sincosf(6.283185307179586f * (float)gid * (1.0f / 1024.0f), &s, &c);
        g_tw[gid] = make_float2(c, -s);
        return;
    }
    int id = gid - 512;
    if (id < N1_) {
        int k = id % 3, i = (id / 3) % 80, o = id / 240;
        float w = W1[id]; g_wT1[(i * 3 + k) * 256 + o] = make_float2(w, w); return;
    }
    id -= N1_;
    if (id < N2_) {
        int k = id % 3, i = (id / 3) % 32, o = id / 96;
        float w = W2[id]; g_wT2[(i * 3 + k) * 256 + o] = make_float2(w, w); return;
    }
    id -= N2_;
    if (id < N3_) {
        int k = id % 3, i = (id / 3) % 32, o = id / 96;
        float w = W3[id]; g_wT3[(i * 3 + k) * 256 + o] = make_float2(w, w); return;
    }
    id -= N3_;
    if (id < N4_) {
        int k = id % 3, i = (id / 3) % 256, o = id / 768;
        float w = W4[id]; g_wT4[(i * 3 + k) * 222 + o] = make_float2(w, w);
    }
}

// ---------------- conv1d 'same' (k=3), 2 output channels per thread ----------------
// 256 threads = 128 o-pairs x 2 time-halves; CTA covers 16 time steps (grid 63x8).
// Dual input tiles: xs0 row = xv[0..17]; xs1 row = xv[1..16] (middle-tap pairs
// pre-shifted in smem -> zero repack MOVs). Weight pair (o,o+1) = one LDG.128.
template <int CIN, int COUT, int GROUPS, bool RELU, bool QUEF>
__global__ void __launch_bounds__(256, 3) conv_kernel(
        const float* __restrict__ in, const float2* __restrict__ WT2,
        const float* __restrict__ bias, float* __restrict__ out) {
    constexpr int CING  = CIN / GROUPS;
    constexpr int GOUT  = COUT / GROUPS;
    constexpr int TCTA  = 16;
    constexpr int ROWS0 = 18;            // xv[0..17], 72B row, 8B-aligned pairs
    constexpr int ROWS1 = 16;            // xv[1..16], 64B row
    constexpr int PAIRS = 4;             // per thread: 8 time steps

    __shared__ __align__(16) float xs0[CIN * ROWS0];
    __shared__ __align__(16) float xs1[CIN * ROWS1];

    const int b    = blockIdx.y;
    const int T0   = blockIdx.x * TCTA;
    const int tid  = threadIdx.x;
    const int half = tid >> 7;           // 0 or 1
    const int op   = tid & 127;          // o-pair index
    const int o    = op * 2;

    // cooperative tile load: xv[tt] = in[b, T0+tt-1, c]
    for (int idx = tid; idx < CIN * ROWS0; idx += 256) {
        int tt = idx / CIN;
        int c  = idx - tt * CIN;
        int t  = T0 + tt - 1;
        float v = 0.0f;
        if (t >= 0 && t < T_) v = in[(b * T_ + t) * CIN + c];
        xs0[c * ROWS0 + tt] = v;
        if (tt >= 1 && tt <= 16) xs1[c * ROWS1 + (tt - 1)] = v;
    }
    __syncthreads();

    if (o >= COUT) return;               // conv4: op in [111,128) idle

    const float bv0 = bias[o], bv1 = bias[o + 1];
    ull ac0[PAIRS], ac1[PAIRS];
    const ull bi0 = pack2(bv0, bv0), bi1 = pack2(bv1, bv1);
#pragma unroll
    for (int p = 0; p < PAIRS; p++) { ac0[p] = bi0; ac1[p] = bi1; }

    const int cbase = (o / GOUT) * CING;
    const float2* wrow = WT2 + o;
    const int poff = half * PAIRS;       // pair offset (4 pairs = 8 time steps)

    for (int i = 0; i < CING; i++) {
        const ull* x0 = reinterpret_cast<const ull*>(xs0 + (cbase + i) * ROWS0) + poff;
        const ull* x1 = reinterpret_cast<const ull*>(xs1 + (cbase + i) * ROWS1) + poff;
        ull a0[PAIRS + 1], a1[PAIRS];
#pragma unroll
        for (int p = 0; p <= PAIRS; p++) a0[p] = x0[p];     // 5 LDS.64
#pragma unroll
        for (int p = 0; p < PAIRS; p++) a1[p] = x1[p];      // 4 LDS.64

        ulonglong2 w0 = *reinterpret_cast<const ulonglong2*>(wrow + (i * 3 + 0) * COUT);
        ulonglong2 w1 = *reinterpret_cast<const ulonglong2*>(wrow + (i * 3 + 1) * COUT);
        ulonglong2 w2 = *reinterpret_cast<const ulonglong2*>(wrow + (i * 3 + 2) * COUT);

#pragma unroll
        for (int p = 0; p < PAIRS; p++) {
            ac0[p] = fma2(w0.x, a0[p],     ac0[p]);
            ac0[p] = fma2(w1.x, a1[p],     ac0[p]);
            ac0[p] = fma2(w2.x, a0[p + 1], ac0[p]);
            ac1[p] = fma2(w0.y, a0[p],     ac1[p]);
            ac1[p] = fma2(w1.y, a1[p],     ac1[p]);
            ac1[p] = fma2(w2.y, a0[p + 1], ac1[p]);
        }
    }

    float rq0 = 1.0f, rq1 = 1.0f;
    if (QUEF) {
        float q0 = (o     < COUT / 2) ? (float)(COUT / 2 - o)     : (float)(o     - COUT / 2 + 1);
        float q1 = (o + 1 < COUT / 2) ? (float)(COUT / 2 - o - 1) : (float)(o + 1 - COUT / 2 + 1);
        rq0 = 1.0f / q0; rq1 = 1.0f / q1;
    }

#pragma unroll
    for (int p = 0; p < PAIRS; p++) {
        float v00, v01, v10, v11;
        unpack2(ac0[p], v00, v01);       // channel o,   times (ta, ta+1)
        unpack2(ac1[p], v10, v11);       // channel o+1
        if (RELU) {
            v00 = fmaxf(v00, 0.0f); v01 = fmaxf(v01, 0.0f);
            v10 = fmaxf(v10, 0.0f); v11 = fmaxf(v11, 0.0f);
        }
        if (QUEF) { v00 *= rq0; v01 *= rq0; v10 *= rq1; v11 *= rq1; }
        int ta = T0 + half * (2 * PAIRS) + 2 * p, tb = ta + 1;
        if (ta < T_)
            *reinterpret_cast<float2*>(out + (long)(b * T_ + ta) * COUT + o) = make_float2(v00, v10);
        if (tb < T_)
            *reinterpret_cast<float2*>(out + (long)(b * T_ + tb) * COUT + o) = make_float2(v01, v11);
    }
}

// ---------------- fused fwd-FFT -> 10^Re * e^{i Im} -> inv-FFT ----------------
// Radix-4 rounds (2 radix-2 stages in registers per smem round).
#define FPHYS(i) ((i) + ((i) >> 5))

__global__ void __launch_bounds__(256) fft_kernel() {
    __shared__ float ar[1056], ai[1056];
    const int row = blockIdx.x;       // 0..7999
    const int tid = threadIdx.x;      // 256

    const float* src = g_cq + (long)row * CCEP_;
    for (int idx = tid; idx < 1024; idx += 256) {
        int j = idx - PAD_;
        float v = (j >= 0 && j < CCEP_) ? src[j] : 0.0f;
        int p = FPHYS(idx);
        ar[p] = v; ai[p] = 0.0f;
    }
    __syncthreads();

    // forward DIF rounds: stage pairs (10,9),(8,7),(6,5),(4,3),(2,1)
#pragma unroll
    for (int s = 10; s >= 2; s -= 2) {
        const int q   = 1 << (s - 2);
        const int pos = tid & (q - 1);
        const int blk = tid >> (s - 2);
        const int i0  = (blk << s) + pos;
        const int p0 = FPHYS(i0), p1 = FPHYS(i0 + q),
                  p2 = FPHYS(i0 + 2 * q), p3 = FPHYS(i0 + 3 * q);

        float x0r = ar[p0], x0i = ai[p0];
        float x1r = ar[p1], x1i = ai[p1];
        float x2r = ar[p2], x2i = ai[p2];
        float x3r = ar[p3], x3i = ai[p3];

        float2 wa = g_tw[pos << (10 - s)];
        float2 wb = g_tw[(pos + q) << (10 - s)];
        float2 wc = g_tw[pos << (11 - s)];

        float t0r = x0r + x2r, t0i = x0i + x2i;
        float dr  = x0r - x2r, di  = x0i - x2i;
        float t2r = dr * wa.x - di * wa.y, t2i = dr * wa.y + di * wa.x;
        float t1r = x1r + x3r, t1i = x1i + x3i;
        dr = x1r - x3r; di = x1i - x3i;
        float t3r = dr * wb.x - di * wb.y, t3i = dr * wb.y + di * wb.x;

        float y0r = t0r + t1r, y0i = t0i + t1i;
        dr = t0r - t1r; di = t0i - t1i;
        float y1r = dr * wc.x - di * wc.y, y1i = dr * wc.y + di * wc.x;
        float y2r = t2r + t3r, y2i = t2i + t3i;
        dr = t2r - t3r; di = t2i - t3i;
        float y3r = dr * wc.x - di * wc.y, y3i = dr * wc.y + di * wc.x;

        __syncthreads();
        ar[p0] = y0r; ai[p0] = y0i;
        ar[p1] = y1r; ai[p1] = y1i;
        ar[p2] = y2r; ai[p2] = y2i;
        ar[p3] = y3r; ai[p3] = y3i;
        __syncthreads();
    }

    // pointwise: S = 10^{Re} * (cos Im, sin Im)
    for (int idx = tid; idx < 1024; idx += 256) {
        int p = FPHYS(idx);
        float mag = __expf(2.302585093f * ar[p]);
        float sn, cs;
        __sincosf(ai[p], &sn, &cs);
        ar[p] = mag * cs; ai[p] = mag * sn;
    }
    __syncthreads();

    // inverse DIT rounds: stage pairs (1,2),(3,4),(5,6),(7,8),(9,10), conj twiddles
#pragma unroll
    for (int s = 1; s <= 9; s += 2) {
        const int q   = 1 << (s - 1);
        const int pos = tid & (q - 1);
        const int blk = tid >> (s - 1);
        const int i0  = (blk << (s + 1)) + pos;
        const int p0 = FPHYS(i0), p1 = FPHYS(i0 + q),
                  p2 = FPHYS(i0 + 2 * q), p3 = FPHYS(i0 + 3 * q);

        float x0r = ar[p0], x0i = ai[p0];
        float x1r = ar[p1], x1i = ai[p1];
        float x2r = ar[p2], x2i = ai[p2];
        float x3r = ar[p3], x3i = ai[p3];

        float2 wa = g_tw[pos << (10 - s)];
        float2 wb = g_tw[pos << (9 - s)];
        float2 wc = g_tw[(pos + q) << (9 - s)];

        float tr = x1r * wa.x + x1i * wa.y, ti = x1i * wa.x - x1r * wa.y;
        float u0r = x0r + tr, u0i = x0i + ti;
        float u1r = x0r - tr, u1i = x0i - ti;
        tr = x3r * wa.x + x3i * wa.y; ti = x3i * wa.x - x3r * wa.y;
        float u2r = x2r + tr, u2i = x2i + ti;
        float u3r = x2r - tr, u3i = x2i - ti;

        tr = u2r * wb.x + u2i * wb.y; ti = u2i * wb.x - u2r * wb.y;
        float y0r = u0r + tr, y0i = u0i + ti;
        float y2r = u0r - tr, y2i = u0i - ti;
        tr = u3r * wc.x + u3i * wc.y; ti = u3i * wc.x - u3r * wc.y;
        float y1r = u1r + tr, y1i = u1i + ti;
        float y3r = u1r - tr, y3i = u1i - ti;

        __syncthreads();
        ar[p0] = y0r; ai[p0] = y0i;
        ar[p1] = y1r; ai[p1] = y1i;
        ar[p2] = y2r; ai[p2] = y2i;
        ar[p3] = y3r; ai[p3] = y3i;
        __syncthreads();
    }

    float* dst = g_imp + (long)row * NF_;
    for (int idx = tid; idx < 1024; idx += 256)
        dst[idx] = ar[FPHYS(idx)] * (1.0f / 1024.0f);
}

// ---------------- direct correlation + Hann window ----------------
#define IPHYS(i) ((i) + (((i) >> 3) << 1))

__global__ void __launch_bounds__(64) corr_kernel(const float* __restrict__ z) {
    __shared__ float fsf[512];
    __shared__ float is[1300];

    const int t = blockIdx.x, b = blockIdx.y;
    const int tid = threadIdx.x;      // 64

    const float* zb = z + (long)b * ZLEN_;
    for (int j = tid; j < 512; j += 64) {
        int src = t * HOP_ + j - 255;
        fsf[j] = (src >= 0 && src < ZLEN_) ? zb[src] : 0.0f;
    }
    const float* ip = g_imp + (long)(b * T_ + t) * NF_;
    for (int j = tid; j < 1024; j += 64)
        is[IPHYS(j)] = ip[j];
    for (int j = 1024 + tid; j < 1040; j += 64)
        is[IPHYS(j)] = 0.0f;
    __syncthreads();

    const ull* fs2 = reinterpret_cast<const ull*>(fsf);
    const int n0 = tid * 8;
    const int base0 = 504 - n0;

    ull P[5];
#pragma unroll
    for (int m = 0; m < 5; m++) {
        int idx = base0 + 2 * m;
        P[m] = *reinterpret_cast<const ull*>(&is[IPHYS(idx)]);
    }
    ull acc[8];
#pragma unroll
    for (int u = 0; u < 8; u++) acc[u] = 0ULL;

#pragma unroll 16
    for (int js = 0; js < 256; js++) {
        ull fd = fs2[js];
        acc[7] = fma2(fd, P[0],             acc[7]);
        acc[6] = fma2(fd, hilo(P[0], P[1]), acc[6]);
        acc[5] = fma2(fd, P[1],             acc[5]);
        acc[4] = fma2(fd, hilo(P[1], P[2]), acc[4]);
        acc[3] = fma2(fd, P[2],             acc[3]);
        acc[2] = fma2(fd, hilo(P[2], P[3]), acc[2]);
        acc[1] = fma2(fd, P[3],             acc[1]);
        acc[0] = fma2(fd, hilo(P[3], P[4]), acc[0]);
        P[0] = P[1]; P[1] = P[2]; P[2] = P[3]; P[3] = P[4];
        int idx = base0 + 2 * js + 10;
        P[4] = *reinterpret_cast<const ull*>(&is[IPHYS(idx)]);
    }

    float* zr = g_zw + (long)(b * T_ + t) * WIN_;
#pragma unroll
    for (int u = 0; u < 8; u++) {
        float v0, v1;
        unpack2(acc[u], v0, v1);
        int n = n0 + u;
        float wn = 0.5f * (1.0f - __cosf(0.0122718463f * (float)n)); // 2*pi/512
        zr[n] = (v0 + v1) * wn;
    }
}

// ---------------- overlap-add with roll(r, 1) on the frame axis ----------------
__global__ void ola_kernel(float* __restrict__ out) {
    const int t = blockIdx.x, b = blockIdx.y, p = threadIdx.x;   // 256 threads
    const int tp = (t == 0) ? (T_ - 1) : (t - 1);
    out[(long)(b * T_ + t) * HOP_ + p] =
        g_zw[(long)(b * T_ + t)  * WIN_ + p] +
        g_zw[(long)(b * T_ + tp) * WIN_ + HOP_ + p];
}

// ---------------- entry point ----------------
extern "C" void kernel_launch(void* const* d_in, const int* in_sizes, int n_in,
                              void* d_out, int out_size) {
    const float* x  = (const float*)d_in[0];
    const float* z  = (const float*)d_in[1];
    const float* W1 = (const float*)d_in[2];
    const float* b1 = (const float*)d_in[3];
    const float* W2 = (const float*)d_in[4];
    const float* b2 = (const float*)d_in[5];
    const float* W3 = (const float*)d_in[6];
    const float* b3 = (const float*)d_in[7];
    const float* W4 = (const float*)d_in[8];
    const float* b4 = (const float*)d_in[9];
    float* out = (float*)d_out;

    float *bufA, *bufB, *cq;
    float2 *wt1, *wt2, *wt3, *wt4;
    cudaGetSymbolAddress((void**)&bufA, g_bufA);
    cudaGetSymbolAddress((void**)&bufB, g_bufB);
    cudaGetSymbolAddress((void**)&cq,   g_cq);
    cudaGetSymbolAddress((void**)&wt1,  g_wT1);
    cudaGetSymbolAddress((void**)&wt2,  g_wT2);
    cudaGetSymbolAddress((void**)&wt3,  g_wT3);
    cudaGetSymbolAddress((void**)&wt4,  g_wT4);

    // fused prep: twiddles + all weight transposes
    prep_kernel<<<1100, 256>>>(W1, W2, W3, W4);

    // 16 time steps per CTA: ceil(1000/16) = 63 blocks in x
    // conv1: 80 -> 256, groups 1, relu
    conv_kernel<80, 256, 1, true, false><<<dim3(63, 8), 256>>>(x, wt1, b1, bufA);
    // conv2: 256 -> 256, groups 8, relu
    conv_kernel<256, 256, 8, true, false><<<dim3(63, 8), 256>>>(bufA, wt2, b2, bufB);
    // conv3: 256 -> 256, groups 8, relu
    conv_kernel<256, 256, 8, true, false><<<dim3(63, 8), 256>>>(bufB, wt3, b3, bufA);
    // conv4: 256 -> 222, groups 1, no relu, quefrency divide
    conv_kernel<256, 222, 1, false, true><<<dim3(63, 8), 256>>>(bufA, wt4, b4, cq);

    // cepstrum -> impulse response (one CTA per (b,t) row)
    fft_kernel<<<8000, 256>>>();

    // direct correlation + window
    corr_kernel<<<dim3(1000, 8), 64>>>(z);

    // overlap-add
    ola_kernel<<<dim3(1000, 8), 256>>>(out);
}

// round 11
// speedup vs baseline: 1.0761x; 1.0761x over previous
#include <cuda_runtime.h>
#include <math.h>

typedef unsigned long long ull;

// Problem constants (fixed shapes)
#define B_    8
#define T_    1000
#define IN_   80
#define CONV_ 256
#define CCEP_ 222
#define HOP_  256
#define WIN_  512
#define NF_   1024
#define PAD_  401
#define ZLEN_ 256000

#define N1_ (80  * 3 * 256)
#define N2_ (32  * 3 * 256)
#define N3_ (32  * 3 * 256)
#define N4_ (256 * 3 * 222)

// ---------------- static device scratch ----------------
__device__ float  g_bufA[B_ * T_ * CONV_];
__device__ float  g_bufB[B_ * T_ * CONV_];
__device__ float  g_cq  [B_ * T_ * CCEP_];
__device__ float  g_imp [B_ * T_ * NF_];
__device__ float  g_zw  [B_ * T_ * WIN_];
__device__ float2 g_tw  [512];
// transposed + duplicated weights: WT2[(i*3+k)*COUT + o] = (w, w)
__device__ __align__(16) float2 g_wT1[N1_];
__device__ __align__(16) float2 g_wT2[N2_];
__device__ __align__(16) float2 g_wT3[N3_];
__device__ __align__(16) float2 g_wT4[N4_];

// ---------------- packed f32x2 helpers ----------------
__device__ __forceinline__ ull pack2(float lo, float hi) {
    ull r; asm("mov.b64 %0, {%1,%2};" : "=l"(r) : "f"(lo), "f"(hi)); return r;
}
__device__ __forceinline__ void unpack2(ull v, float& lo, float& hi) {
    asm("mov.b64 {%0,%1}, %2;" : "=f"(lo), "=f"(hi) : "l"(v));
}
__device__ __forceinline__ ull fma2(ull a, ull b, ull c) {
    ull d; asm("fma.rn.f32x2 %0, %1, %2, %3;" : "=l"(d) : "l"(a), "l"(b), "l"(c)); return d;
}
// (a.hi, b.lo)
__device__ __forceinline__ ull hilo(ull a, ull b) {
    float al, ah, bl, bh;
    unpack2(a, al, ah); unpack2(b, bl, bh);
    return pack2(ah, bl);
}

// ---------------- fused prep: twiddles + 4 weight transposes ----------------
__global__ void prep_kernel(const float* __restrict__ W1, const float* __restrict__ W2,
                            const float* __restrict__ W3, const float* __restrict__ W4) {
    int gid = blockIdx.x * 256 + threadIdx.x;
    if (gid < 512) {
        float s, c;
        sincosf(6.283185307179586f * (float)gid * (1.0f / 1024.0f), &s, &c);
        g_tw[gid] = make_float2(c, -s);
        return;
    }
    int id = gid - 512;
    if (id < N1_) {
        int k = id % 3, i = (id / 3) % 80, o = id / 240;
        float w = W1[id]; g_wT1[(i * 3 + k) * 256 + o] = make_float2(w, w); return;
    }
    id -= N1_;
    if (id < N2_) {
        int k = id % 3, i = (id / 3) % 32, o = id / 96;
        float w = W2[id]; g_wT2[(i * 3 + k) * 256 + o] = make_float2(w, w); return;
    }
    id -= N2_;
    if (id < N3_) {
        int k = id % 3, i = (id / 3) % 32, o = id / 96;
        float w = W3[id]; g_wT3[(i * 3 + k) * 256 + o] = make_float2(w, w); return;
    }
    id -= N3_;
    if (id < N4_) {
        int k = id % 3, i = (id / 3) % 256, o = id / 768;
        float w = W4[id]; g_wT4[(i * 3 + k) * 222 + o] = make_float2(w, w);
    }
}

// ---------------- conv1d 'same' (k=3), 2 output channels per thread ----------------
// 512 threads = 128 o-pairs x 4 time-quarters; CTA covers 32 time steps (grid 32x8).
// Dual input tiles (dynamic smem): xs0 row = xv[0..33]; xs1 row = xv[1..32]
// (middle-tap pairs pre-shifted -> zero repack MOVs).
// Weight pair (o,o+1) = one LDG.128; the 4 quarter-threads hit the same line.
template <int CIN, int COUT, int GROUPS, bool RELU, bool QUEF>
__global__ void __launch_bounds__(512, 2) conv_kernel(
        const float* __restrict__ in, const float2* __restrict__ WT2,
        const float* __restrict__ bias, float* __restrict__ out) {
    constexpr int CING  = CIN / GROUPS;
    constexpr int GOUT  = COUT / GROUPS;
    constexpr int TCTA  = 32;
    constexpr int ROWS0 = 34;            // xv[0..33], 136B row, 8B-aligned pairs
    constexpr int ROWS1 = 32;            // xv[1..32], 128B row
    constexpr int PAIRS = 4;             // per thread: 8 time steps

    extern __shared__ __align__(16) float smem_f[];
    float* xs0 = smem_f;                 // CIN * ROWS0
    float* xs1 = smem_f + CIN * ROWS0;   // CIN * ROWS1 (CIN*34 even -> 8B aligned)

    const int b    = blockIdx.y;
    const int T0   = blockIdx.x * TCTA;
    const int tid  = threadIdx.x;
    const int quar = tid >> 7;           // 0..3
    const int op   = tid & 127;          // o-pair index
    const int o    = op * 2;

    // cooperative tile load: xv[tt] = in[b, T0+tt-1, c]  (coalesced over c)
    for (int idx = tid; idx < CIN * ROWS0; idx += 512) {
        int tt = idx / CIN;
        int c  = idx - tt * CIN;
        int t  = T0 + tt - 1;
        float v = 0.0f;
        if (t >= 0 && t < T_) v = in[(b * T_ + t) * CIN + c];
        xs0[c * ROWS0 + tt] = v;
        if (tt >= 1 && tt <= 32) xs1[c * ROWS1 + (tt - 1)] = v;
    }
    __syncthreads();

    if (o >= COUT) return;               // conv4: op in [111,128) idle

    const float bv0 = bias[o], bv1 = bias[o + 1];
    ull ac0[PAIRS], ac1[PAIRS];
    const ull bi0 = pack2(bv0, bv0), bi1 = pack2(bv1, bv1);
#pragma unroll
    for (int p = 0; p < PAIRS; p++) { ac0[p] = bi0; ac1[p] = bi1; }

    const int cbase = (o / GOUT) * CING;
    const float2* wrow = WT2 + o;
    const int poff = quar * PAIRS;       // pair offset (4 pairs = 8 time steps)

    for (int i = 0; i < CING; i++) {
        const ull* x0 = reinterpret_cast<const ull*>(xs0 + (cbase + i) * ROWS0) + poff;
        const ull* x1 = reinterpret_cast<const ull*>(xs1 + (cbase + i) * ROWS1) + poff;
        ull a0[PAIRS + 1], a1[PAIRS];
#pragma unroll
        for (int p = 0; p <= PAIRS; p++) a0[p] = x0[p];     // 5 LDS.64 (broadcast)
#pragma unroll
        for (int p = 0; p < PAIRS; p++) a1[p] = x1[p];      // 4 LDS.64

        ulonglong2 w0 = *reinterpret_cast<const ulonglong2*>(wrow + (i * 3 + 0) * COUT);
        ulonglong2 w1 = *reinterpret_cast<const ulonglong2*>(wrow + (i * 3 + 1) * COUT);
        ulonglong2 w2 = *reinterpret_cast<const ulonglong2*>(wrow + (i * 3 + 2) * COUT);

#pragma unroll
        for (int p = 0; p < PAIRS; p++) {
            ac0[p] = fma2(w0.x, a0[p],     ac0[p]);
            ac0[p] = fma2(w1.x, a1[p],     ac0[p]);
            ac0[p] = fma2(w2.x, a0[p + 1], ac0[p]);
            ac1[p] = fma2(w0.y, a0[p],     ac1[p]);
            ac1[p] = fma2(w1.y, a1[p],     ac1[p]);
            ac1[p] = fma2(w2.y, a0[p + 1], ac1[p]);
        }
    }

    float rq0 = 1.0f, rq1 = 1.0f;
    if (QUEF) {
        float q0 = (o     < COUT / 2) ? (float)(COUT / 2 - o)     : (float)(o     - COUT / 2 + 1);
        float q1 = (o + 1 < COUT / 2) ? (float)(COUT / 2 - o - 1) : (float)(o + 1 - COUT / 2 + 1);
        rq0 = 1.0f / q0; rq1 = 1.0f / q1;
    }

#pragma unroll
    for (int p = 0; p < PAIRS; p++) {
        float v00, v01, v10, v11;
        unpack2(ac0[p], v00, v01);       // channel o,   times (ta, ta+1)
        unpack2(ac1[p], v10, v11);       // channel o+1
        if (RELU) {
            v00 = fmaxf(v00, 0.0f); v01 = fmaxf(v01, 0.0f);
            v10 = fmaxf(v10, 0.0f); v11 = fmaxf(v11, 0.0f);
        }
        if (QUEF) { v00 *= rq0; v01 *= rq0; v10 *= rq1; v11 *= rq1; }
        int ta = T0 + quar * (2 * PAIRS) + 2 * p, tb = ta + 1;
        if (ta < T_)
            *reinterpret_cast<float2*>(out + (long)(b * T_ + ta) * COUT + o) = make_float2(v00, v10);
        if (tb < T_)
            *reinterpret_cast<float2*>(out + (long)(b * T_ + tb) * COUT + o) = make_float2(v01, v11);
    }
}

// ---------------- fused fwd-FFT -> 10^Re * e^{i Im} -> inv-FFT ----------------
// Radix-4 rounds (2 radix-2 stages in registers per smem round).
#define FPHYS(i) ((i) + ((i) >> 5))

__global__ void __launch_bounds__(256) fft_kernel() {
    __shared__ float ar[1056], ai[1056];
    const int row = blockIdx.x;       // 0..7999
    const int tid = threadIdx.x;      // 256

    const float* src = g_cq + (long)row * CCEP_;
    for (int idx = tid; idx < 1024; idx += 256) {
        int j = idx - PAD_;
        float v = (j >= 0 && j < CCEP_) ? src[j] : 0.0f;
        int p = FPHYS(idx);
        ar[p] = v; ai[p] = 0.0f;
    }
    __syncthreads();

    // forward DIF rounds: stage pairs (10,9),(8,7),(6,5),(4,3),(2,1)
#pragma unroll
    for (int s = 10; s >= 2; s -= 2) {
        const int q   = 1 << (s - 2);
        const int pos = tid & (q - 1);
        const int blk = tid >> (s - 2);
        const int i0  = (blk << s) + pos;
        const int p0 = FPHYS(i0), p1 = FPHYS(i0 + q),
                  p2 = FPHYS(i0 + 2 * q), p3 = FPHYS(i0 + 3 * q);

        float x0r = ar[p0], x0i = ai[p0];
        float x1r = ar[p1], x1i = ai[p1];
        float x2r = ar[p2], x2i = ai[p2];
        float x3r = ar[p3], x3i = ai[p3];

        float2 wa = g_tw[pos << (10 - s)];
        float2 wb = g_tw[(pos + q) << (10 - s)];
        float2 wc = g_tw[pos << (11 - s)];

        float t0r = x0r + x2r, t0i = x0i + x2i;
        float dr  = x0r - x2r, di  = x0i - x2i;
        float t2r = dr * wa.x - di * wa.y, t2i = dr * wa.y + di * wa.x;
        float t1r = x1r + x3r, t1i = x1i + x3i;
        dr = x1r - x3r; di = x1i - x3i;
        float t3r = dr * wb.x - di * wb.y, t3i = dr * wb.y + di * wb.x;

        float y0r = t0r + t1r, y0i = t0i + t1i;
        dr = t0r - t1r; di = t0i - t1i;
        float y1r = dr * wc.x - di * wc.y, y1i = dr * wc.y + di * wc.x;
        float y2r = t2r + t3r, y2i = t2i + t3i;
        dr = t2r - t3r; di = t2i - t3i;
        float y3r = dr * wc.x - di * wc.y, y3i = dr * wc.y + di * wc.x;

        __syncthreads();
        ar[p0] = y0r; ai[p0] = y0i;
        ar[p1] = y1r; ai[p1] = y1i;
        ar[p2] = y2r; ai[p2] = y2i;
        ar[p3] = y3r; ai[p3] = y3i;
        __syncthreads();
    }

    // pointwise: S = 10^{Re} * (cos Im, sin Im)
    for (int idx = tid; idx < 1024; idx += 256) {
        int p = FPHYS(idx);
        float mag = __expf(2.302585093f * ar[p]);
        float sn, cs;
        __sincosf(ai[p], &sn, &cs);
        ar[p] = mag * cs; ai[p] = mag * sn;
    }
    __syncthreads();

    // inverse DIT rounds: stage pairs (1,2),(3,4),(5,6),(7,8),(9,10), conj twiddles
#pragma unroll
    for (int s = 1; s <= 9; s += 2) {
        const int q   = 1 << (s - 1);
        const int pos = tid & (q - 1);
        const int blk = tid >> (s - 1);
        const int i0  = (blk << (s + 1)) + pos;
        const int p0 = FPHYS(i0), p1 = FPHYS(i0 + q),
                  p2 = FPHYS(i0 + 2 * q), p3 = FPHYS(i0 + 3 * q);

        float x0r = ar[p0], x0i = ai[p0];
        float x1r = ar[p1], x1i = ai[p1];
        float x2r = ar[p2], x2i = ai[p2];
        float x3r = ar[p3], x3i = ai[p3];

        float2 wa = g_tw[pos << (10 - s)];
        float2 wb = g_tw[pos << (9 - s)];
        float2 wc = g_tw[(pos + q) << (9 - s)];

        float tr = x1r * wa.x + x1i * wa.y, ti = x1i * wa.x - x1r * wa.y;
        float u0r = x0r + tr, u0i = x0i + ti;
        float u1r = x0r - tr, u1i = x0i - ti;
        tr = x3r * wa.x + x3i * wa.y; ti = x3i * wa.x - x3r * wa.y;
        float u2r = x2r + tr, u2i = x2i + ti;
        float u3r = x2r - tr, u3i = x2i - ti;

        tr = u2r * wb.x + u2i * wb.y; ti = u2i * wb.x - u2r * wb.y;
        float y0r = u0r + tr, y0i = u0i + ti;
        float y2r = u0r - tr, y2i = u0i - ti;
        tr = u3r * wc.x + u3i * wc.y; ti = u3i * wc.x - u3r * wc.y;
        float y1r = u1r + tr, y1i = u1i + ti;
        float y3r = u1r - tr, y3i = u1i - ti;

        __syncthreads();
        ar[p0] = y0r; ai[p0] = y0i;
        ar[p1] = y1r; ai[p1] = y1i;
        ar[p2] = y2r; ai[p2] = y2i;
        ar[p3] = y3r; ai[p3] = y3i;
        __syncthreads();
    }

    float* dst = g_imp + (long)row * NF_;
    for (int idx = tid; idx < 1024; idx += 256)
        dst[idx] = ar[FPHYS(idx)] * (1.0f / 1024.0f);
}

// ---------------- direct correlation + Hann window ----------------
#define IPHYS(i) ((i) + (((i) >> 3) << 1))

__global__ void __launch_bounds__(64) corr_kernel(const float* __restrict__ z) {
    __shared__ float fsf[512];
    __shared__ float is[1300];

    const int t = blockIdx.x, b = blockIdx.y;
    const int tid = threadIdx.x;      // 64

    const float* zb = z + (long)b * ZLEN_;
    for (int j = tid; j < 512; j += 64) {
        int src = t * HOP_ + j - 255;
        fsf[j] = (src >= 0 && src < ZLEN_) ? zb[src] : 0.0f;
    }
    const float* ip = g_imp + (long)(b * T_ + t) * NF_;
    for (int j = tid; j < 1024; j += 64)
        is[IPHYS(j)] = ip[j];
    for (int j = 1024 + tid; j < 1040; j += 64)
        is[IPHYS(j)] = 0.0f;
    __syncthreads();

    const ull* fs2 = reinterpret_cast<const ull*>(fsf);
    const int n0 = tid * 8;
    const int base0 = 504 - n0;

    ull P[5];
#pragma unroll
    for (int m = 0; m < 5; m++) {
        int idx = base0 + 2 * m;
        P[m] = *reinterpret_cast<const ull*>(&is[IPHYS(idx)]);
    }
    ull acc[8];
#pragma unroll
    for (int u = 0; u < 8; u++) acc[u] = 0ULL;

#pragma unroll 16
    for (int js = 0; js < 256; js++) {
        ull fd = fs2[js];
        acc[7] = fma2(fd, P[0],             acc[7]);
        acc[6] = fma2(fd, hilo(P[0], P[1]), acc[6]);
        acc[5] = fma2(fd, P[1],             acc[5]);
        acc[4] = fma2(fd, hilo(P[1], P[2]), acc[4]);
        acc[3] = fma2(fd, P[2],             acc[3]);
        acc[2] = fma2(fd, hilo(P[2], P[3]), acc[2]);
        acc[1] = fma2(fd, P[3],             acc[1]);
        acc[0] = fma2(fd, hilo(P[3], P[4]), acc[0]);
        P[0] = P[1]; P[1] = P[2]; P[2] = P[3]; P[3] = P[4];
        int idx = base0 + 2 * js + 10;
        P[4] = *reinterpret_cast<const ull*>(&is[IPHYS(idx)]);
    }

    float* zr = g_zw + (long)(b * T_ + t) * WIN_;
#pragma unroll
    for (int u = 0; u < 8; u++) {
        float v0, v1;
        unpack2(acc[u], v0, v1);
        int n = n0 + u;
        float wn = 0.5f * (1.0f - __cosf(0.0122718463f * (float)n)); // 2*pi/512
        zr[n] = (v0 + v1) * wn;
    }
}

// ---------------- overlap-add with roll(r, 1) on the frame axis ----------------
__global__ void ola_kernel(float* __restrict__ out) {
    const int t = blockIdx.x, b = blockIdx.y, p = threadIdx.x;   // 256 threads
    const int tp = (t == 0) ? (T_ - 1) : (t - 1);
    out[(long)(b * T_ + t) * HOP_ + p] =
        g_zw[(long)(b * T_ + t)  * WIN_ + p] +
        g_zw[(long)(b * T_ + tp) * WIN_ + HOP_ + p];
}

// ---------------- entry point ----------------
extern "C" void kernel_launch(void* const* d_in, const int* in_sizes, int n_in,
                              void* d_out, int out_size) {
    const float* x  = (const float*)d_in[0];
    const float* z  = (const float*)d_in[1];
    const float* W1 = (const float*)d_in[2];
    const float* b1 = (const float*)d_in[3];
    const float* W2 = (const float*)d_in[4];
    const float* b2 = (const float*)d_in[5];
    const float* W3 = (const float*)d_in[6];
    const float* b3 = (const float*)d_in[7];
    const float* W4 = (const float*)d_in[8];
    const float* b4 = (const float*)d_in[9];
    float* out = (float*)d_out;

    float *bufA, *bufB, *cq;
    float2 *wt1, *wt2, *wt3, *wt4;
    cudaGetSymbolAddress((void**)&bufA, g_bufA);
    cudaGetSymbolAddress((void**)&bufB, g_bufB);
    cudaGetSymbolAddress((void**)&cq,   g_cq);
    cudaGetSymbolAddress((void**)&wt1,  g_wT1);
    cudaGetSymbolAddress((void**)&wt2,  g_wT2);
    cudaGetSymbolAddress((void**)&wt3,  g_wT3);
    cudaGetSymbolAddress((void**)&wt4,  g_wT4);

    // dynamic smem sizes (xs0 + xs1)
    const int smem80  = (80  * 34 + 80  * 32) * 4;   // 21.1 KB
    const int smem256 = (256 * 34 + 256 * 32) * 4;   // 67.6 KB

    static bool attr_done = false;
    if (!attr_done) {
        cudaFuncSetAttribute((const void*)&conv_kernel<256, 256, 8, true, false>,
                             cudaFuncAttributeMaxDynamicSharedMemorySize, smem256);
        cudaFuncSetAttribute((const void*)&conv_kernel<256, 222, 1, false, true>,
                             cudaFuncAttributeMaxDynamicSharedMemorySize, smem256);
        attr_done = true;
    }

    // fused prep: twiddles + all weight transposes
    prep_kernel<<<1100, 256>>>(W1, W2, W3, W4);

    // 32 time steps per CTA: 32 blocks in x, 512 threads (128 o-pairs x 4 quarters)
    // conv1: 80 -> 256, groups 1, relu
    conv_kernel<80, 256, 1, true, false><<<dim3(32, 8), 512, smem80>>>(x, wt1, b1, bufA);
    // conv2: 256 -> 256, groups 8, relu
    conv_kernel<256, 256, 8, true, false><<<dim3(32, 8), 512, smem256>>>(bufA, wt2, b2, bufB);
    // conv3: 256 -> 256, groups 8, relu
    conv_kernel<256, 256, 8, true, false><<<dim3(32, 8), 512, smem256>>>(bufB, wt3, b3, bufA);
    // conv4: 256 -> 222, groups 1, no relu, quefrency divide
    conv_kernel<256, 222, 1, false, true><<<dim3(32, 8), 512, smem256>>>(bufA, wt4, b4, cq);

    // cepstrum -> impulse response (one CTA per (b,t) row)
    fft_kernel<<<8000, 256>>>();

    // direct correlation + window
    corr_kernel<<<dim3(1000, 8), 64>>>(z);

    // overlap-add
    ola_kernel<<<dim3(1000, 8), 256>>>(out);
}

// round 12
// speedup vs baseline: 1.0787x; 1.0024x over previous
#include <cuda_runtime.h>
#include <math.h>

typedef unsigned long long ull;

// Problem constants (fixed shapes)
#define B_    8
#define T_    1000
#define IN_   80
#define CONV_ 256
#define CCEP_ 222
#define HOP_  256
#define WIN_  512
#define NF_   1024
#define PAD_  401
#define ZLEN_ 256000

#define N1_ (80  * 3 * 256)
#define N2_ (32  * 3 * 256)
#define N3_ (32  * 3 * 256)
#define N4_ (256 * 3 * 222)

// ---------------- static device scratch ----------------
__device__ float  g_bufA[B_ * T_ * CONV_];
__device__ float  g_bufB[B_ * T_ * CONV_];
__device__ float  g_cq  [B_ * T_ * CCEP_];
__device__ float  g_imp [B_ * T_ * NF_];
__device__ float  g_zw  [B_ * T_ * WIN_];
__device__ float2 g_tw  [512];
// transposed scalar weights: WT[(i*3+k)*COUT + o] = w
__device__ __align__(16) float g_wS1[N1_];
__device__ __align__(16) float g_wS2[N2_];
__device__ __align__(16) float g_wS3[N3_];
__device__ __align__(16) float g_wS4[N4_];

// ---------------- packed f32x2 helpers ----------------
__device__ __forceinline__ ull pack2(float lo, float hi) {
    ull r; asm("mov.b64 %0, {%1,%2};" : "=l"(r) : "f"(lo), "f"(hi)); return r;
}
__device__ __forceinline__ void unpack2(ull v, float& lo, float& hi) {
    asm("mov.b64 {%0,%1}, %2;" : "=f"(lo), "=f"(hi) : "l"(v));
}
__device__ __forceinline__ ull fma2(ull a, ull b, ull c) {
    ull d; asm("fma.rn.f32x2 %0, %1, %2, %3;" : "=l"(d) : "l"(a), "l"(b), "l"(c)); return d;
}

// ---------------- fused prep: twiddles + 4 weight transposes (scalar) ----------------
__global__ void prep_kernel(const float* __restrict__ W1, const float* __restrict__ W2,
                            const float* __restrict__ W3, const float* __restrict__ W4) {
    int gid = blockIdx.x * 256 + threadIdx.x;
    if (gid < 512) {
        float s, c;
        sincosf(6.283185307179586f * (float)gid * (1.0f / 1024.0f), &s, &c);
        g_tw[gid] = make_float2(c, -s);
        return;
    }
    int id = gid - 512;
    if (id < N1_) {
        int k = id % 3, i = (id / 3) % 80, o = id / 240;
        g_wS1[(i * 3 + k) * 256 + o] = W1[id]; return;
    }
    id -= N1_;
    if (id < N2_) {
        int k = id % 3, i = (id / 3) % 32, o = id / 96;
        g_wS2[(i * 3 + k) * 256 + o] = W2[id]; return;
    }
    id -= N2_;
    if (id < N3_) {
        int k = id % 3, i = (id / 3) % 32, o = id / 96;
        g_wS3[(i * 3 + k) * 256 + o] = W3[id]; return;
    }
    id -= N3_;
    if (id < N4_) {
        int k = id % 3, i = (id / 3) % 256, o = id / 768;
        g_wS4[(i * 3 + k) * 222 + o] = W4[id];
    }
}

// ---------------- conv1d 'same' (k=3), one output channel per thread ----------------
// o = tid: each warp covers 32 consecutive channels = exactly one group (GOUT=32
// or GROUPS=1) -> every LDS is a true warp-broadcast (1 wavefront).
// Dual tiles, both vectorized as LDS.128:
//   xs0 row = xv[0..17] padded to 20 floats (80B: every row 16B-aligned)
//   xs1 row = xv[1..16] = 16 floats (64B)
// Scalar weight LDG.32 (coalesced, 128B/warp) + dup-MOV on the idle ALU pipe.
template <int CIN, int COUT, int GROUPS, bool RELU, bool QUEF>
__global__ void __launch_bounds__(256, 3) conv_kernel(
        const float* __restrict__ in, const float* __restrict__ WT,
        const float* __restrict__ bias, float* __restrict__ out) {
    constexpr int CING  = CIN / GROUPS;
    constexpr int GOUT  = COUT / GROUPS;
    constexpr int TCTA  = 16;
    constexpr int ROWS0 = 20;            // xv[0..17] + 2 pad floats
    constexpr int ROWS1 = 16;            // xv[1..16]
    constexpr int PAIRS = 8;

    __shared__ __align__(16) float xs0[CIN * ROWS0];
    __shared__ __align__(16) float xs1[CIN * ROWS1];

    const int b   = blockIdx.y;
    const int T0  = blockIdx.x * TCTA;
    const int tid = threadIdx.x;

    // cooperative tile load: xv[tt] = in[b, T0+tt-1, c]   (coalesced over c)
    for (int idx = tid; idx < CIN * 18; idx += 256) {
        int tt = idx / CIN;
        int c  = idx - tt * CIN;
        int t  = T0 + tt - 1;
        float v = 0.0f;
        if (t >= 0 && t < T_) v = in[(b * T_ + t) * CIN + c];
        xs0[c * ROWS0 + tt] = v;
        if (tt >= 1 && tt <= 16) xs1[c * ROWS1 + (tt - 1)] = v;
    }
    __syncthreads();

    const int o = tid;
    if (o >= COUT) return;               // conv4: o in [222,256) idle

    const float bv = bias[o];
    const ull binit = pack2(bv, bv);
    ull acc[PAIRS];
#pragma unroll
    for (int p = 0; p < PAIRS; p++) acc[p] = binit;

    const int cbase = (o / GOUT) * CING;
    const float* wp = WT + o;

    for (int i = 0; i < CING; i++) {
        const float4* x0 = reinterpret_cast<const float4*>(xs0 + (cbase + i) * ROWS0);
        const float4* x1 = reinterpret_cast<const float4*>(xs1 + (cbase + i) * ROWS1);
        float xf0[20], xf1[16];
#pragma unroll
        for (int k = 0; k < 5; k++) *reinterpret_cast<float4*>(xf0 + 4 * k) = x0[k];  // 5x LDS.128 broadcast
#pragma unroll
        for (int k = 0; k < 4; k++) *reinterpret_cast<float4*>(xf1 + 4 * k) = x1[k];  // 4x LDS.128 broadcast
        const ull* a0 = reinterpret_cast<const ull*>(xf0);   // pairs (xv[2p], xv[2p+1])
        const ull* a1 = reinterpret_cast<const ull*>(xf1);   // pairs (xv[2p+1], xv[2p+2])

        float w0s = wp[(i * 3 + 0) * COUT];
        float w1s = wp[(i * 3 + 1) * COUT];
        float w2s = wp[(i * 3 + 2) * COUT];
        ull w0 = pack2(w0s, w0s), w1 = pack2(w1s, w1s), w2 = pack2(w2s, w2s);

#pragma unroll
        for (int p = 0; p < PAIRS; p++) {
            acc[p] = fma2(w0, a0[p],     acc[p]);
            acc[p] = fma2(w1, a1[p],     acc[p]);
            acc[p] = fma2(w2, a0[p + 1], acc[p]);
        }
    }

    float rq = 1.0f;
    if (QUEF) {
        float q = (o < COUT / 2) ? (float)(COUT / 2 - o) : (float)(o - COUT / 2 + 1);
        rq = 1.0f / q;
    }

#pragma unroll
    for (int p = 0; p < PAIRS; p++) {
        float v0, v1;
        unpack2(acc[p], v0, v1);
        if (RELU) { v0 = fmaxf(v0, 0.0f); v1 = fmaxf(v1, 0.0f); }
        if (QUEF) { v0 *= rq; v1 *= rq; }
        int ta = T0 + 2 * p, tb = ta + 1;
        if (ta < T_) out[(long)(b * T_ + ta) * COUT + o] = v0;
        if (tb < T_) out[(long)(b * T_ + tb) * COUT + o] = v1;
    }
}

// ---------------- fused fwd-FFT -> 10^Re * e^{i Im} -> inv-FFT ----------------
// Radix-4 rounds (2 radix-2 stages in registers per smem round).
#define FPHYS(i) ((i) + ((i) >> 5))

__global__ void __launch_bounds__(256) fft_kernel() {
    __shared__ float ar[1056], ai[1056];
    const int row = blockIdx.x;       // 0..7999
    const int tid = threadIdx.x;      // 256

    const float* src = g_cq + (long)row * CCEP_;
    for (int idx = tid; idx < 1024; idx += 256) {
        int j = idx - PAD_;
        float v = (j >= 0 && j < CCEP_) ? src[j] : 0.0f;
        int p = FPHYS(idx);
        ar[p] = v; ai[p] = 0.0f;
    }
    __syncthreads();

    // forward DIF rounds: stage pairs (10,9),(8,7),(6,5),(4,3),(2,1)
#pragma unroll
    for (int s = 10; s >= 2; s -= 2) {
        const int q   = 1 << (s - 2);
        const int pos = tid & (q - 1);
        const int blk = tid >> (s - 2);
        const int i0  = (blk << s) + pos;
        const int p0 = FPHYS(i0), p1 = FPHYS(i0 + q),
                  p2 = FPHYS(i0 + 2 * q), p3 = FPHYS(i0 + 3 * q);

        float x0r = ar[p0], x0i = ai[p0];
        float x1r = ar[p1], x1i = ai[p1];
        float x2r = ar[p2], x2i = ai[p2];
        float x3r = ar[p3], x3i = ai[p3];

        float2 wa = g_tw[pos << (10 - s)];
        float2 wb = g_tw[(pos + q) << (10 - s)];
        float2 wc = g_tw[pos << (11 - s)];

        float t0r = x0r + x2r, t0i = x0i + x2i;
        float dr  = x0r - x2r, di  = x0i - x2i;
        float t2r = dr * wa.x - di * wa.y, t2i = dr * wa.y + di * wa.x;
        float t1r = x1r + x3r, t1i = x1i + x3i;
        dr = x1r - x3r; di = x1i - x3i;
        float t3r = dr * wb.x - di * wb.y, t3i = dr * wb.y + di * wb.x;

        float y0r = t0r + t1r, y0i = t0i + t1i;
        dr = t0r - t1r; di = t0i - t1i;
        float y1r = dr * wc.x - di * wc.y, y1i = dr * wc.y + di * wc.x;
        float y2r = t2r + t3r, y2i = t2i + t3i;
        dr = t2r - t3r; di = t2i - t3i;
        float y3r = dr * wc.x - di * wc.y, y3i = dr * wc.y + di * wc.x;

        __syncthreads();
        ar[p0] = y0r; ai[p0] = y0i;
        ar[p1] = y1r; ai[p1] = y1i;
        ar[p2] = y2r; ai[p2] = y2i;
        ar[p3] = y3r; ai[p3] = y3i;
        __syncthreads();
    }

    // pointwise: S = 10^{Re} * (cos Im, sin Im)
    for (int idx = tid; idx < 1024; idx += 256) {
        int p = FPHYS(idx);
        float mag = __expf(2.302585093f * ar[p]);
        float sn, cs;
        __sincosf(ai[p], &sn, &cs);
        ar[p] = mag * cs; ai[p] = mag * sn;
    }
    __syncthreads();

    // inverse DIT rounds: stage pairs (1,2),(3,4),(5,6),(7,8),(9,10), conj twiddles
#pragma unroll
    for (int s = 1; s <= 9; s += 2) {
        const int q   = 1 << (s - 1);
        const int pos = tid & (q - 1);
        const int blk = tid >> (s - 1);
        const int i0  = (blk << (s + 1)) + pos;
        const int p0 = FPHYS(i0), p1 = FPHYS(i0 + q),
                  p2 = FPHYS(i0 + 2 * q), p3 = FPHYS(i0 + 3 * q);

        float x0r = ar[p0], x0i = ai[p0];
        float x1r = ar[p1], x1i = ai[p1];
        float x2r = ar[p2], x2i = ai[p2];
        float x3r = ar[p3], x3i = ai[p3];

        float2 wa = g_tw[pos << (10 - s)];
        float2 wb = g_tw[pos << (9 - s)];
        float2 wc = g_tw[(pos + q) << (9 - s)];

        float tr = x1r * wa.x + x1i * wa.y, ti = x1i * wa.x - x1r * wa.y;
        float u0r = x0r + tr, u0i = x0i + ti;
        float u1r = x0r - tr, u1i = x0i - ti;
        tr = x3r * wa.x + x3i * wa.y; ti = x3i * wa.x - x3r * wa.y;
        float u2r = x2r + tr, u2i = x2i + ti;
        float u3r = x2r - tr, u3i = x2i - ti;

        tr = u2r * wb.x + u2i * wb.y; ti = u2i * wb.x - u2r * wb.y;
        float y0r = u0r + tr, y0i = u0i + ti;
        float y2r = u0r - tr, y2i = u0i - ti;
        tr = u3r * wc.x + u3i * wc.y; ti = u3i * wc.x - u3r * wc.y;
        float y1r = u1r + tr, y1i = u1i + ti;
        float y3r = u1r - tr, y3i = u1i - ti;

        __syncthreads();
        ar[p0] = y0r; ai[p0] = y0i;
        ar[p1] = y1r; ai[p1] = y1i;
        ar[p2] = y2r; ai[p2] = y2i;
        ar[p3] = y3r; ai[p3] = y3i;
        __syncthreads();
    }

    float* dst = g_imp + (long)row * NF_;
    for (int idx = tid; idx < 1024; idx += 256)
        dst[idx] = ar[FPHYS(idx)] * (1.0f / 1024.0f);
}

// ---------------- direct correlation + Hann window ----------------
// corr[n] = sum_j frame[j]*imp[j+511-n]. Accumulators packed over (even j, odd j).
// TWO imp copies: is0[j]=imp[j], is1[j]=imp[j+1] -> odd-lag operand pairs are
// aligned LDS.64 too: zero repack MOVs in the hot loop.
#define IPHYS(i) ((i) + (((i) >> 3) << 1))

__global__ void __launch_bounds__(64) corr_kernel(const float* __restrict__ z) {
    __shared__ float fsf[512];
    __shared__ float is0[1300];
    __shared__ float is1[1300];

    const int t = blockIdx.x, b = blockIdx.y;
    const int tid = threadIdx.x;      // 64

    const float* zb = z + (long)b * ZLEN_;
    for (int j = tid; j < 512; j += 64) {
        int src = t * HOP_ + j - 255;
        fsf[j] = (src >= 0 && src < ZLEN_) ? zb[src] : 0.0f;
    }
    const float* ip = g_imp + (long)(b * T_ + t) * NF_;
    for (int j = tid; j < 1040; j += 64) {
        is0[IPHYS(j)] = (j < 1024) ? ip[j] : 0.0f;
        is1[IPHYS(j)] = (j + 1 < 1024) ? ip[j + 1] : 0.0f;
    }
    __syncthreads();

    const ull* fs2 = reinterpret_cast<const ull*>(fsf);
    const int n0 = tid * 8;
    const int base0 = 504 - n0;          // even window start

    ull P0[5], P1[4];
#pragma unroll
    for (int m = 0; m < 5; m++)
        P0[m] = *reinterpret_cast<const ull*>(&is0[IPHYS(base0 + 2 * m)]);
#pragma unroll
    for (int m = 0; m < 4; m++)
        P1[m] = *reinterpret_cast<const ull*>(&is1[IPHYS(base0 + 2 * m)]);

    ull acc[8];
#pragma unroll
    for (int u = 0; u < 8; u++) acc[u] = 0ULL;

#pragma unroll 16
    for (int js = 0; js < 256; js++) {
        ull fd = fs2[js];
        acc[7] = fma2(fd, P0[0], acc[7]);   // pair at idx
        acc[6] = fma2(fd, P1[0], acc[6]);   // pair at idx+1
        acc[5] = fma2(fd, P0[1], acc[5]);
        acc[4] = fma2(fd, P1[1], acc[4]);
        acc[3] = fma2(fd, P0[2], acc[3]);
        acc[2] = fma2(fd, P1[2], acc[2]);
        acc[1] = fma2(fd, P0[3], acc[1]);
        acc[0] = fma2(fd, P1[3], acc[0]);
        P0[0] = P0[1]; P0[1] = P0[2]; P0[2] = P0[3]; P0[3] = P0[4];
        P1[0] = P1[1]; P1[1] = P1[2]; P1[2] = P1[3];
        int idx = base0 + 2 * js;
        P0[4] = *reinterpret_cast<const ull*>(&is0[IPHYS(idx + 10)]);
        P1[3] = *reinterpret_cast<const ull*>(&is1[IPHYS(idx + 8)]);
    }

    float* zr = g_zw + (long)(b * T_ + t) * WIN_;
#pragma unroll
    for (int u = 0; u < 8; u++) {
        float v0, v1;
        unpack2(acc[u], v0, v1);
        int n = n0 + u;
        float wn = 0.5f * (1.0f - __cosf(0.0122718463f * (float)n)); // 2*pi/512
        zr[n] = (v0 + v1) * wn;
    }
}

// ---------------- overlap-add with roll(r, 1) on the frame axis ----------------
__global__ void ola_kernel(float* __restrict__ out) {
    const int t = blockIdx.x, b = blockIdx.y, p = threadIdx.x;   // 256 threads
    const int tp = (t == 0) ? (T_ - 1) : (t - 1);
    out[(long)(b * T_ + t) * HOP_ + p] =
        g_zw[(long)(b * T_ + t)  * WIN_ + p] +
        g_zw[(long)(b * T_ + tp) * WIN_ + HOP_ + p];
}

// ---------------- entry point ----------------
extern "C" void kernel_launch(void* const* d_in, const int* in_sizes, int n_in,
                              void* d_out, int out_size) {
    const float* x  = (const float*)d_in[0];
    const float* z  = (const float*)d_in[1];
    const float* W1 = (const float*)d_in[2];
    const float* b1 = (const float*)d_in[3];
    const float* W2 = (const float*)d_in[4];
    const float* b2 = (const float*)d_in[5];
    const float* W3 = (const float*)d_in[6];
    const float* b3 = (const float*)d_in[7];
    const float* W4 = (const float*)d_in[8];
    const float* b4 = (const float*)d_in[9];
    float* out = (float*)d_out;

    float *bufA, *bufB, *cq, *ws1, *ws2, *ws3, *ws4;
    cudaGetSymbolAddress((void**)&bufA, g_bufA);
    cudaGetSymbolAddress((void**)&bufB, g_bufB);
    cudaGetSymbolAddress((void**)&cq,   g_cq);
    cudaGetSymbolAddress((void**)&ws1,  g_wS1);
    cudaGetSymbolAddress((void**)&ws2,  g_wS2);
    cudaGetSymbolAddress((void**)&ws3,  g_wS3);
    cudaGetSymbolAddress((void**)&ws4,  g_wS4);

    // fused prep: twiddles + all weight transposes
    prep_kernel<<<1100, 256>>>(W1, W2, W3, W4);

    // 16 time steps per CTA: ceil(1000/16) = 63 blocks in x, 256 threads
    // conv1: 80 -> 256, groups 1, relu
    conv_kernel<80, 256, 1, true, false><<<dim3(63, 8), 256>>>(x, ws1, b1, bufA);
    // conv2: 256 -> 256, groups 8, relu
    conv_kernel<256, 256, 8, true, false><<<dim3(63, 8), 256>>>(bufA, ws2, b2, bufB);
    // conv3: 256 -> 256, groups 8, relu
    conv_kernel<256, 256, 8, true, false><<<dim3(63, 8), 256>>>(bufB, ws3, b3, bufA);
    // conv4: 256 -> 222, groups 1, no relu, quefrency divide
    conv_kernel<256, 222, 1, false, true><<<dim3(63, 8), 256>>>(bufA, ws4, b4, cq);

    // cepstrum -> impulse response (one CTA per (b,t) row)
    fft_kernel<<<8000, 256>>>();

    // direct correlation + window
    corr_kernel<<<dim3(1000, 8), 64>>>(z);

    // overlap-add
    ola_kernel<<<dim3(1000, 8), 256>>>(out);
}

// round 13
// speedup vs baseline: 1.1178x; 1.0363x over previous
#include <cuda_runtime.h>
#include <math.h>

typedef unsigned long long ull;

// Problem constants (fixed shapes)
#define B_    8
#define T_    1000
#define IN_   80
#define CONV_ 256
#define CCEP_ 222
#define HOP_  256
#define WIN_  512
#define NF_   1024
#define PAD_  401
#define ZLEN_ 256000

#define N1_ (80  * 3 * 256)
#define N2_ (32  * 3 * 256)
#define N3_ (32  * 3 * 256)
#define N4_ (256 * 3 * 222)

// ---------------- static device scratch ----------------
__device__ float  g_bufA[B_ * T_ * CONV_];
__device__ float  g_bufB[B_ * T_ * CONV_];
__device__ float  g_cq  [B_ * T_ * CCEP_];
__device__ float  g_imp [B_ * T_ * NF_];
__device__ float  g_zw  [B_ * T_ * WIN_];
__device__ float2 g_tw  [512];
// transposed + duplicated weights: WT2[(i*3+k)*COUT + o] = (w, w)
__device__ __align__(16) float2 g_wT1[N1_];
__device__ __align__(16) float2 g_wT2[N2_];
__device__ __align__(16) float2 g_wT3[N3_];
__device__ __align__(16) float2 g_wT4[N4_];

// ---------------- packed f32x2 helpers ----------------
__device__ __forceinline__ ull pack2(float lo, float hi) {
    ull r; asm("mov.b64 %0, {%1,%2};" : "=l"(r) : "f"(lo), "f"(hi)); return r;
}
__device__ __forceinline__ void unpack2(ull v, float& lo, float& hi) {
    asm("mov.b64 {%0,%1}, %2;" : "=f"(lo), "=f"(hi) : "l"(v));
}
__device__ __forceinline__ ull fma2(ull a, ull b, ull c) {
    ull d; asm("fma.rn.f32x2 %0, %1, %2, %3;" : "=l"(d) : "l"(a), "l"(b), "l"(c)); return d;
}

// ---------------- fused prep: twiddles + 4 weight transposes (dup float2) --------
__global__ void prep_kernel(const float* __restrict__ W1, const float* __restrict__ W2,
                            const float* __restrict__ W3, const float* __restrict__ W4) {
    int gid = blockIdx.x * 256 + threadIdx.x;
    if (gid < 512) {
        float s, c;
        sincosf(6.283185307179586f * (float)gid * (1.0f / 1024.0f), &s, &c);
        g_tw[gid] = make_float2(c, -s);
        return;
    }
    int id = gid - 512;
    if (id < N1_) {
        int k = id % 3, i = (id / 3) % 80, o = id / 240;
        float w = W1[id]; g_wT1[(i * 3 + k) * 256 + o] = make_float2(w, w); return;
    }
    id -= N1_;
    if (id < N2_) {
        int k = id % 3, i = (id / 3) % 32, o = id / 96;
        float w = W2[id]; g_wT2[(i * 3 + k) * 256 + o] = make_float2(w, w); return;
    }
    id -= N2_;
    if (id < N3_) {
        int k = id % 3, i = (id / 3) % 32, o = id / 96;
        float w = W3[id]; g_wT3[(i * 3 + k) * 256 + o] = make_float2(w, w); return;
    }
    id -= N3_;
    if (id < N4_) {
        int k = id % 3, i = (id / 3) % 256, o = id / 768;
        float w = W4[id]; g_wT4[(i * 3 + k) * 222 + o] = make_float2(w, w);
    }
}

// ---------------- conv1d 'same' (k=3), one output channel per thread ----------------
// Proven R8 structure. NTHREADS = 256*NHALF threads; each o-channel handled by
// NHALF threads covering TCTA = 16*NHALF time steps (8 pairs each).
// Dual tiles (dynamic smem): xs0 row = xv[0..TCTA+1]; xs1 row = xv[1..TCTA]
// (middle-tap pairs pre-shifted in smem -> zero repack MOVs).
// Weight pair for channel o is the dup-(w,w) layout: one LDG.64 per tap, 256B/warp;
// extra halves re-hit the same lines in L1 (no added L2 traffic).
template <int CIN, int COUT, int GROUPS, int NHALF, bool RELU, bool QUEF>
__global__ void __launch_bounds__(256 * NHALF) conv_kernel(
        const float* __restrict__ in, const float2* __restrict__ WT2,
        const float* __restrict__ bias, float* __restrict__ out) {
    constexpr int CING  = CIN / GROUPS;
    constexpr int GOUT  = COUT / GROUPS;
    constexpr int TCTA  = 16 * NHALF;
    constexpr int ROWS0 = TCTA + 2;      // xv[0..TCTA+1]
    constexpr int ROWS1 = TCTA;          // xv[1..TCTA]
    constexpr int PAIRS = 8;
    constexpr int NT    = 256 * NHALF;

    extern __shared__ __align__(16) float smem_f[];
    float* xs0 = smem_f;                 // CIN * ROWS0
    float* xs1 = smem_f + CIN * ROWS0;   // CIN * ROWS1

    const int b    = blockIdx.y;
    const int T0   = blockIdx.x * TCTA;
    const int tid  = threadIdx.x;
    const int half = tid >> 8;           // 0..NHALF-1
    const int o    = tid & 255;

    // cooperative tile load: xv[tt] = in[b, T0+tt-1, c]  (coalesced over c)
    for (int idx = tid; idx < CIN * ROWS0; idx += NT) {
        int tt = idx / CIN;
        int c  = idx - tt * CIN;
        int t  = T0 + tt - 1;
        float v = 0.0f;
        if (t >= 0 && t < T_) v = in[(b * T_ + t) * CIN + c];
        xs0[c * ROWS0 + tt] = v;
        if (tt >= 1 && tt <= TCTA) xs1[c * ROWS1 + (tt - 1)] = v;
    }
    __syncthreads();

    if (o >= COUT) return;               // conv4: o in [222,256) idle

    const float bv = bias[o];
    const ull binit = pack2(bv, bv);
    ull ac[PAIRS];
#pragma unroll
    for (int p = 0; p < PAIRS; p++) ac[p] = binit;

    const int cbase = (o / GOUT) * CING;
    const float2* wp = WT2 + o;
    const int poff = half * PAIRS;       // pair offset within the row

    for (int i = 0; i < CING; i++) {
        const ull* x0 = reinterpret_cast<const ull*>(xs0 + (cbase + i) * ROWS0) + poff;
        const ull* x1 = reinterpret_cast<const ull*>(xs1 + (cbase + i) * ROWS1) + poff;
        ull a0[PAIRS + 1], a1[PAIRS];
#pragma unroll
        for (int p = 0; p <= PAIRS; p++) a0[p] = x0[p];     // 9 LDS.64, warp-broadcast
#pragma unroll
        for (int p = 0; p < PAIRS; p++) a1[p] = x1[p];      // 8 LDS.64, warp-broadcast

        ull W0 = *reinterpret_cast<const ull*>(&wp[(i * 3 + 0) * COUT]);
        ull W1 = *reinterpret_cast<const ull*>(&wp[(i * 3 + 1) * COUT]);
        ull W2 = *reinterpret_cast<const ull*>(&wp[(i * 3 + 2) * COUT]);

#pragma unroll
        for (int p = 0; p < PAIRS; p++) {
            ac[p] = fma2(W0, a0[p],     ac[p]);
            ac[p] = fma2(W1, a1[p],     ac[p]);
            ac[p] = fma2(W2, a0[p + 1], ac[p]);
        }
    }

    float rq = 1.0f;
    if (QUEF) {
        float q = (o < COUT / 2) ? (float)(COUT / 2 - o) : (float)(o - COUT / 2 + 1);
        rq = 1.0f / q;
    }

#pragma unroll
    for (int p = 0; p < PAIRS; p++) {
        float v0, v1;
        unpack2(ac[p], v0, v1);
        if (RELU) { v0 = fmaxf(v0, 0.0f); v1 = fmaxf(v1, 0.0f); }
        if (QUEF) { v0 *= rq; v1 *= rq; }
        int ta = T0 + half * 16 + 2 * p, tb = ta + 1;
        if (ta < T_) out[(long)(b * T_ + ta) * COUT + o] = v0;
        if (tb < T_) out[(long)(b * T_ + tb) * COUT + o] = v1;
    }
}

// ---------------- fused fwd-FFT -> 10^Re * e^{i Im} -> inv-FFT ----------------
// Radix-4 rounds (2 radix-2 stages in registers per smem round).
#define FPHYS(i) ((i) + ((i) >> 5))

__global__ void __launch_bounds__(256) fft_kernel() {
    __shared__ float ar[1056], ai[1056];
    const int row = blockIdx.x;       // 0..7999
    const int tid = threadIdx.x;      // 256

    const float* src = g_cq + (long)row * CCEP_;
    for (int idx = tid; idx < 1024; idx += 256) {
        int j = idx - PAD_;
        float v = (j >= 0 && j < CCEP_) ? src[j] : 0.0f;
        int p = FPHYS(idx);
        ar[p] = v; ai[p] = 0.0f;
    }
    __syncthreads();

    // forward DIF rounds: stage pairs (10,9),(8,7),(6,5),(4,3),(2,1)
#pragma unroll
    for (int s = 10; s >= 2; s -= 2) {
        const int q   = 1 << (s - 2);
        const int pos = tid & (q - 1);
        const int blk = tid >> (s - 2);
        const int i0  = (blk << s) + pos;
        const int p0 = FPHYS(i0), p1 = FPHYS(i0 + q),
                  p2 = FPHYS(i0 + 2 * q), p3 = FPHYS(i0 + 3 * q);

        float x0r = ar[p0], x0i = ai[p0];
        float x1r = ar[p1], x1i = ai[p1];
        float x2r = ar[p2], x2i = ai[p2];
        float x3r = ar[p3], x3i = ai[p3];

        float2 wa = g_tw[pos << (10 - s)];
        float2 wb = g_tw[(pos + q) << (10 - s)];
        float2 wc = g_tw[pos << (11 - s)];

        float t0r = x0r + x2r, t0i = x0i + x2i;
        float dr  = x0r - x2r, di  = x0i - x2i;
        float t2r = dr * wa.x - di * wa.y, t2i = dr * wa.y + di * wa.x;
        float t1r = x1r + x3r, t1i = x1i + x3i;
        dr = x1r - x3r; di = x1i - x3i;
        float t3r = dr * wb.x - di * wb.y, t3i = dr * wb.y + di * wb.x;

        float y0r = t0r + t1r, y0i = t0i + t1i;
        dr = t0r - t1r; di = t0i - t1i;
        float y1r = dr * wc.x - di * wc.y, y1i = dr * wc.y + di * wc.x;
        float y2r = t2r + t3r, y2i = t2i + t3i;
        dr = t2r - t3r; di = t2i - t3i;
        float y3r = dr * wc.x - di * wc.y, y3i = dr * wc.y + di * wc.x;

        __syncthreads();
        ar[p0] = y0r; ai[p0] = y0i;
        ar[p1] = y1r; ai[p1] = y1i;
        ar[p2] = y2r; ai[p2] = y2i;
        ar[p3] = y3r; ai[p3] = y3i;
        __syncthreads();
    }

    // pointwise: S = 10^{Re} * (cos Im, sin Im)
    for (int idx = tid; idx < 1024; idx += 256) {
        int p = FPHYS(idx);
        float mag = __expf(2.302585093f * ar[p]);
        float sn, cs;
        __sincosf(ai[p], &sn, &cs);
        ar[p] = mag * cs; ai[p] = mag * sn;
    }
    __syncthreads();

    // inverse DIT rounds: stage pairs (1,2),(3,4),(5,6),(7,8),(9,10), conj twiddles
#pragma unroll
    for (int s = 1; s <= 9; s += 2) {
        const int q   = 1 << (s - 1);
        const int pos = tid & (q - 1);
        const int blk = tid >> (s - 1);
        const int i0  = (blk << (s + 1)) + pos;
        const int p0 = FPHYS(i0), p1 = FPHYS(i0 + q),
                  p2 = FPHYS(i0 + 2 * q), p3 = FPHYS(i0 + 3 * q);

        float x0r = ar[p0], x0i = ai[p0];
        float x1r = ar[p1], x1i = ai[p1];
        float x2r = ar[p2], x2i = ai[p2];
        float x3r = ar[p3], x3i = ai[p3];

        float2 wa = g_tw[pos << (10 - s)];
        float2 wb = g_tw[pos << (9 - s)];
        float2 wc = g_tw[(pos + q) << (9 - s)];

        float tr = x1r * wa.x + x1i * wa.y, ti = x1i * wa.x - x1r * wa.y;
        float u0r = x0r + tr, u0i = x0i + ti;
        float u1r = x0r - tr, u1i = x0i - ti;
        tr = x3r * wa.x + x3i * wa.y; ti = x3i * wa.x - x3r * wa.y;
        float u2r = x2r + tr, u2i = x2i + ti;
        float u3r = x2r - tr, u3i = x2i - ti;

        tr = u2r * wb.x + u2i * wb.y; ti = u2i * wb.x - u2r * wb.y;
        float y0r = u0r + tr, y0i = u0i + ti;
        float y2r = u0r - tr, y2i = u0i - ti;
        tr = u3r * wc.x + u3i * wc.y; ti = u3i * wc.x - u3r * wc.y;
        float y1r = u1r + tr, y1i = u1i + ti;
        float y3r = u1r - tr, y3i = u1i - ti;

        __syncthreads();
        ar[p0] = y0r; ai[p0] = y0i;
        ar[p1] = y1r; ai[p1] = y1i;
        ar[p2] = y2r; ai[p2] = y2i;
        ar[p3] = y3r; ai[p3] = y3i;
        __syncthreads();
    }

    float* dst = g_imp + (long)row * NF_;
    for (int idx = tid; idx < 1024; idx += 256)
        dst[idx] = ar[FPHYS(idx)] * (1.0f / 1024.0f);
}

// ---------------- direct correlation + Hann window ----------------
// corr[n] = sum_j frame[j]*imp[j+511-n]. Accumulators packed over (even j, odd j).
// TWO imp copies: is0[j]=imp[j], is1[j]=imp[j+1] -> both lag parities use
// aligned LDS.64: zero repack MOVs in the hot loop.
#define IPHYS(i) ((i) + (((i) >> 3) << 1))

__global__ void __launch_bounds__(64) corr_kernel(const float* __restrict__ z) {
    __shared__ float fsf[512];
    __shared__ float is0[1300];
    __shared__ float is1[1300];

    const int t = blockIdx.x, b = blockIdx.y;
    const int tid = threadIdx.x;      // 64

    const float* zb = z + (long)b * ZLEN_;
    for (int j = tid; j < 512; j += 64) {
        int src = t * HOP_ + j - 255;
        fsf[j] = (src >= 0 && src < ZLEN_) ? zb[src] : 0.0f;
    }
    const float* ip = g_imp + (long)(b * T_ + t) * NF_;
    for (int j = tid; j < 1040; j += 64) {
        is0[IPHYS(j)] = (j < 1024) ? ip[j] : 0.0f;
        is1[IPHYS(j)] = (j + 1 < 1024) ? ip[j + 1] : 0.0f;
    }
    __syncthreads();

    const ull* fs2 = reinterpret_cast<const ull*>(fsf);
    const int n0 = tid * 8;
    const int base0 = 504 - n0;          // even window start

    ull P0[5], P1[4];
#pragma unroll
    for (int m = 0; m < 5; m++)
        P0[m] = *reinterpret_cast<const ull*>(&is0[IPHYS(base0 + 2 * m)]);
#pragma unroll
    for (int m = 0; m < 4; m++)
        P1[m] = *reinterpret_cast<const ull*>(&is1[IPHYS(base0 + 2 * m)]);

    ull acc[8];
#pragma unroll
    for (int u = 0; u < 8; u++) acc[u] = 0ULL;

#pragma unroll 16
    for (int js = 0; js < 256; js++) {
        ull fd = fs2[js];
        acc[7] = fma2(fd, P0[0], acc[7]);
        acc[6] = fma2(fd, P1[0], acc[6]);
        acc[5] = fma2(fd, P0[1], acc[5]);
        acc[4] = fma2(fd, P1[1], acc[4]);
        acc[3] = fma2(fd, P0[2], acc[3]);
        acc[2] = fma2(fd, P1[2], acc[2]);
        acc[1] = fma2(fd, P0[3], acc[1]);
        acc[0] = fma2(fd, P1[3], acc[0]);
        P0[0] = P0[1]; P0[1] = P0[2]; P0[2] = P0[3]; P0[3] = P0[4];
        P1[0] = P1[1]; P1[1] = P1[2]; P1[2] = P1[3];
        int idx = base0 + 2 * js;
        P0[4] = *reinterpret_cast<const ull*>(&is0[IPHYS(idx + 10)]);
        P1[3] = *reinterpret_cast<const ull*>(&is1[IPHYS(idx + 8)]);
    }

    float* zr = g_zw + (long)(b * T_ + t) * WIN_;
#pragma unroll
    for (int u = 0; u < 8; u++) {
        float v0, v1;
        unpack2(acc[u], v0, v1);
        int n = n0 + u;
        float wn = 0.5f * (1.0f - __cosf(0.0122718463f * (float)n)); // 2*pi/512
        zr[n] = (v0 + v1) * wn;
    }
}

// ---------------- overlap-add with roll(r, 1) on the frame axis ----------------
__global__ void ola_kernel(float* __restrict__ out) {
    const int t = blockIdx.x, b = blockIdx.y, p = threadIdx.x;   // 256 threads
    const int tp = (t == 0) ? (T_ - 1) : (t - 1);
    out[(long)(b * T_ + t) * HOP_ + p] =
        g_zw[(long)(b * T_ + t)  * WIN_ + p] +
        g_zw[(long)(b * T_ + tp) * WIN_ + HOP_ + p];
}

// ---------------- entry point ----------------
extern "C" void kernel_launch(void* const* d_in, const int* in_sizes, int n_in,
                              void* d_out, int out_size) {
    const float* x  = (const float*)d_in[0];
    const float* z  = (const float*)d_in[1];
    const float* W1 = (const float*)d_in[2];
    const float* b1 = (const float*)d_in[3];
    const float* W2 = (const float*)d_in[4];
    const float* b2 = (const float*)d_in[5];
    const float* W3 = (const float*)d_in[6];
    const float* b3 = (const float*)d_in[7];
    const float* W4 = (const float*)d_in[8];
    const float* b4 = (const float*)d_in[9];
    float* out = (float*)d_out;

    float *bufA, *bufB, *cq;
    float2 *wt1, *wt2, *wt3, *wt4;
    cudaGetSymbolAddress((void**)&bufA, g_bufA);
    cudaGetSymbolAddress((void**)&bufB, g_bufB);
    cudaGetSymbolAddress((void**)&cq,   g_cq);
    cudaGetSymbolAddress((void**)&wt1,  g_wT1);
    cudaGetSymbolAddress((void**)&wt2,  g_wT2);
    cudaGetSymbolAddress((void**)&wt3,  g_wT3);
    cudaGetSymbolAddress((void**)&wt4,  g_wT4);

    // dynamic smem: xs0 (CIN*(TCTA+2)) + xs1 (CIN*TCTA) floats
    const int smem1  = (80  * 18 + 80  * 16) * 4;   // 10.9 KB  (TCTA=16)
    const int smem23 = (256 * 18 + 256 * 16) * 4;   // 34.8 KB  (TCTA=16)
    const int smem4  = (256 * 34 + 256 * 32) * 4;   // 67.6 KB  (TCTA=32)

    static bool attr_done = false;
    if (!attr_done) {
        cudaFuncSetAttribute((const void*)&conv_kernel<256, 222, 1, 2, false, true>,
                             cudaFuncAttributeMaxDynamicSharedMemorySize, smem4);
        attr_done = true;
    }

    // fused prep: twiddles + all weight transposes
    prep_kernel<<<1100, 256>>>(W1, W2, W3, W4);

    // conv1: 80 -> 256, groups 1, relu            (R8 form, TCTA=16)
    conv_kernel<80, 256, 1, 1, true, false><<<dim3(63, 8), 256, smem1>>>(x, wt1, b1, bufA);
    // conv2: 256 -> 256, groups 8, relu           (R8 form, TCTA=16)
    conv_kernel<256, 256, 8, 1, true, false><<<dim3(63, 8), 256, smem23>>>(bufA, wt2, b2, bufB);
    // conv3: 256 -> 256, groups 8, relu           (R8 form, TCTA=16)
    conv_kernel<256, 256, 8, 1, true, false><<<dim3(63, 8), 256, smem23>>>(bufB, wt3, b3, bufA);
    // conv4: 256 -> 222, groups 1, quefrency      (TCTA=32, 512 threads: halves
    //        weight L2 traffic, the dominant cost for CING=256)
    conv_kernel<256, 222, 1, 2, false, true><<<dim3(32, 8), 512, smem4>>>(bufA, wt4, b4, cq);

    // cepstrum -> impulse response (one CTA per (b,t) row)
    fft_kernel<<<8000, 256>>>();

    // direct correlation + window
    corr_kernel<<<dim3(1000, 8), 64>>>(z);

    // overlap-add
    ola_kernel<<<dim3(1000, 8), 256>>>(out);
}